// round 9
// baseline (speedup 1.0000x reference)
#include <cuda_runtime.h>

#define MASK  511
#define W_IMG 512
#define PLANE (512 * 512)

#define R_OUT     4                      // out rows per warp
#define WARPS     4
#define TILE_ROWS 16                     // out rows per block
#define OUT_COLS  60                     // out cols per block (lanes 1..30, 2 each)
#define TROWS     30                     // 16 + 2*7 halo
#define TCOLS     76                     // 75 used + 1 pad (even => 8B alignment holds)
#define TPIX      (TROWS * TCOLS)        // 2280
#define FULLM     0xffffffffu

typedef unsigned long long u64;

__device__ __forceinline__ u64 pk(float a, float b) {
    u64 r; asm("mov.b64 %0, {%1, %2};" : "=l"(r) : "f"(a), "f"(b)); return r;
}
__device__ __forceinline__ void up2(u64 v, float& a, float& b) {
    asm("mov.b64 {%0, %1}, %2;" : "=f"(a), "=f"(b) : "l"(v));
}
__device__ __forceinline__ u64 fma2(u64 a, u64 b, u64 c) {
    u64 d; asm("fma.rn.f32x2 %0, %1, %2, %3;" : "=l"(d) : "l"(a), "l"(b), "l"(c)); return d;
}
__device__ __forceinline__ u64 mul2(u64 a, u64 b) {
    u64 d; asm("mul.rn.f32x2 %0, %1, %2;" : "=l"(d) : "l"(a), "l"(b)); return d;
}
__device__ __forceinline__ u64 add2(u64 a, u64 b) {
    u64 d; asm("add.rn.f32x2 %0, %1, %2;" : "=l"(d) : "l"(a), "l"(b)); return d;
}
__device__ __forceinline__ float fsqrt_ap(float x) {
    float r; asm("sqrt.approx.f32 %0, %1;" : "=f"(r) : "f"(x)); return r;
}
// ex2 of the NEGATED input; ptxas folds the neg into the operand modifier
__device__ __forceinline__ float fex2n(float x) {
    float r; asm("ex2.approx.f32 %0, %1;" : "=f"(r) : "f"(-x)); return r;
}

#define NEG1 0xBF800000BF800000ULL               /* {-1.f,-1.f} */
#define YSCL 0.4808983469629878f                 /* log2(e)/3: pre-folded into y */

// One horizontal offset ox, all 11 oy, R_OUT=4 rows.
// shy : pair-aligned shifted-y base (for odd ox it's the ysB shift-by-1 plane).
// x*0 : channel plane + x fetch column (even either parity => aligned LDS.64).
// ODD : accumulation targets cols (cx+1,cx+2) [phase B] vs (cx,cx+1) [phase A].
template<bool ODD>
__device__ __forceinline__ void process_ox(
    const float* __restrict__ shy,
    const float* __restrict__ xr0, const float* __restrict__ xg0,
    const float* __restrict__ xb0,
    const u64* __restrict__ yreg, int r0t,
    u64* aW, u64* aR, u64* aG, u64* aB)
{
    // ---- ysh ring: 8 active shifted-y pair rows (row m -> slot m&7) ----
    u64 ysh[8];
    #pragma unroll
    for (int m = 0; m < 8; ++m)
        ysh[m] = *(const u64*)&shy[(r0t + m) * TCOLS];

    // ---- x ring: 4 active rows per channel (row r0t+2+m -> slot m&3) ----
    u64 xrg[4], xgg[4], xbg[4];
    #pragma unroll
    for (int m = 0; m < 4; ++m) {
        xrg[m] = *(const u64*)&xr0[(r0t + 2 + m) * TCOLS];
        xgg[m] = *(const u64*)&xg0[(r0t + 2 + m) * TCOLS];
        xbg[m] = *(const u64*)&xb0[(r0t + 2 + m) * TCOLS];
    }

    #pragma unroll
    for (int oyi = 0; oyi < 11; ++oyi) {         // oy = oyi - 5
        // stage 0: advance rings (loads issue early, consumed much later)
        if (oyi > 0) {
            ysh[(oyi + 7) & 7] = *(const u64*)&shy[(r0t + oyi + 7) * TCOLS];
            const int xrow = (r0t + 5 + oyi) * TCOLS;
            xrg[(oyi + 3) & 3] = *(const u64*)&xr0[xrow];
            xgg[(oyi + 3) & 3] = *(const u64*)&xg0[xrow];
            xbg[(oyi + 3) & 3] = *(const u64*)&xb0[xrow];
        }

        // stage 1: squared luminance diffs (scaled), own rows r0t+5..r0t+12
        u64 s[8];
        #pragma unroll
        for (int j = 0; j < 8; ++j) {
            u64 d = fma2(NEG1, ysh[(j + oyi) & 7], yreg[j]);
            s[j]  = mul2(d, d);
        }

        // stage 2: vertical sliding 5-sums
        u64 v5[4];
        u64 vs = add2(add2(s[0], s[1]), add2(s[2], s[3]));
        v5[0] = add2(vs, s[4]); vs = fma2(NEG1, s[0], v5[0]);
        v5[1] = add2(vs, s[5]); vs = fma2(NEG1, s[1], v5[1]);
        v5[2] = add2(vs, s[6]); vs = fma2(NEG1, s[2], v5[2]);
        v5[3] = add2(vs, s[7]);

        // stage 3: unpack + pair sums
        float va[4], vb[4], t[4];
        #pragma unroll
        for (int k = 0; k < 4; ++k) { up2(v5[k], va[k], vb[k]); t[k] = va[k] + vb[k]; }

        // stage 4: batched shuffles + horizontal 5-sums
        float d2[8];
        #pragma unroll
        for (int k = 0; k < 4; ++k) {
            if (!ODD) {
                float cm = __shfl_up_sync  (FULLM, t[k], 1);
                float cp = __shfl_down_sync(FULLM, t[k], 1);
                float ap = __shfl_down_sync(FULLM, va[k], 1);
                float bm = __shfl_up_sync  (FULLM, vb[k], 1);
                d2[2 * k]     = (cm + t[k]) + ap;        // col cx
                d2[2 * k + 1] = (bm + t[k]) + cp;        // col cx+1
            } else {
                float cp = __shfl_down_sync(FULLM, t[k], 1);
                float bm = __shfl_up_sync  (FULLM, vb[k], 1);
                float a2 = __shfl_down_sync(FULLM, va[k], 2);
                d2[2 * k]     = (bm + t[k]) + cp;        // col cx+1
                d2[2 * k + 1] = (t[k] + cp) + a2;        // col cx+2
            }
        }

        // stage 5: MUFU chains, batched so latencies overlap
        float q[8];
        #pragma unroll
        for (int i = 0; i < 8; ++i) q[i] = fsqrt_ap(d2[i]);
        float w[8];
        #pragma unroll
        for (int i = 0; i < 8; ++i) w[i] = fex2n(q[i]);  // e^(-dist/3)

        // stage 6: accumulate (x operands from the ring)
        #pragma unroll
        for (int k = 0; k < 4; ++k) {
            u64 w2 = pk(w[2 * k], w[2 * k + 1]);
            aW[k] = add2(aW[k], w2);
            aR[k] = fma2(w2, xrg[(oyi + k) & 3], aR[k]);
            aG[k] = fma2(w2, xgg[(oyi + k) & 3], aG[k]);
            aB[k] = fma2(w2, xbg[(oyi + k) & 3], aB[k]);
        }
    }
}

__global__ __launch_bounds__(32 * WARPS, 4)
void nlm_kernel(const float* __restrict__ x, float* __restrict__ out)
{
    __shared__ __align__(16) float smem[5 * TPIX];   // ys | ysB | xr | xg | xb
    float* ys  = smem;
    float* ysB = smem + TPIX;                        // ysB[r][c] = ys[r][c+1]
    float* xr  = smem + 2 * TPIX;
    float* xg  = smem + 3 * TPIX;
    float* xb  = smem + 4 * TPIX;

    const int lane = threadIdx.x;
    const int warp = threadIdx.y;
    const int tid  = warp * 32 + lane;

    const int n       = blockIdx.z;
    const int rowBase = blockIdx.y * TILE_ROWS;
    const int colBase = blockIdx.x * OUT_COLS;
    const int rowTop  = rowBase - 7 + 512;
    const int colLeft = colBase - 8 + 512;

    const float* xbase = x + (size_t)n * 3 * PLANE;

    for (int idx = tid; idx < TPIX; idx += 32 * WARPS) {
        int r  = idx / TCOLS;
        int c  = idx - r * TCOLS;
        int gy = (rowTop + r) & MASK;
        int gx = (colLeft + c) & MASK;
        const float* p = xbase + gy * W_IMG + gx;
        float rv = p[0];
        float gv = p[PLANE];
        float bv = p[2 * PLANE];
        float rc = fminf(fmaxf(rv, 0.f), 1.f);
        float gc = fminf(fmaxf(gv, 0.f), 1.f);
        float bc = fminf(fmaxf(bv, 0.f), 1.f);
        // luminance pre-scaled by log2(e)/3 so the weight is ex2(-sqrt(d2))
        float yv = (0.299f * YSCL) * rc + (0.587f * YSCL) * gc + (0.114f * YSCL) * bc;
        xr[idx] = rv; xg[idx] = gv; xb[idx] = bv; ys[idx] = yv;
        if (c) ysB[idx - 1] = yv;
    }
    __syncthreads();

    const int r0t = warp * R_OUT;          // warp's out-row start (tile row +7)
    const int cx  = 6 + 2 * lane;          // own pair: tile cols (cx, cx+1)

    // own pairs (scaled), template rows r0t+5 .. r0t+12
    u64 yreg[8];
    #pragma unroll
    for (int j = 0; j < 8; ++j)
        yreg[j] = *(const u64*)&ys[(r0t + 5 + j) * TCOLS + cx];

    u64 aW[4], aR[4], aG[4], aB[4];        // single set; starts in phase-B layout
    #pragma unroll
    for (int k = 0; k < 4; ++k) { aW[k] = 0ULL; aR[k] = 0ULL; aG[k] = 0ULL; aB[k] = 0ULL; }

    // ---- odd offsets first, phase-B layout: cols (cx+1, cx+2) ----
    #pragma unroll 1
    for (int ox = -5; ox <= 5; ox += 2)
        process_ox<true>(ysB + cx + ox - 1,
                         xr + cx + ox + 1, xg + cx + ox + 1, xb + cx + ox + 1,
                         yreg, r0t, aW, aR, aG, aB);

    // ---- re-align phase B -> phase A: lane L's lo(cx) = lane L-1's hi ----
    #pragma unroll
    for (int k = 0; k < 4; ++k) {
        float lo, hi;
        up2(aW[k], lo, hi); aW[k] = pk(__shfl_up_sync(FULLM, hi, 1), lo);
        up2(aR[k], lo, hi); aR[k] = pk(__shfl_up_sync(FULLM, hi, 1), lo);
        up2(aG[k], lo, hi); aG[k] = pk(__shfl_up_sync(FULLM, hi, 1), lo);
        up2(aB[k], lo, hi); aB[k] = pk(__shfl_up_sync(FULLM, hi, 1), lo);
    }

    // ---- even offsets, phase-A layout: cols (cx, cx+1) ----
    #pragma unroll 1
    for (int ox = -4; ox <= 4; ox += 2)
        process_ox<false>(ys + cx + ox,
                          xr + cx + ox, xg + cx + ox, xb + cx + ox,
                          yreg, r0t, aW, aR, aG, aB);

    // ---- write output (lanes 1..30 own 60 output cols) ----
    if (lane >= 1 && lane <= 30) {
        int gc = (colBase + 2 * (lane - 1)) & MASK;   // even; pair contiguous
        float* ob = out + (size_t)n * 3 * PLANE;
        #pragma unroll
        for (int k = 0; k < 4; ++k) {
            float wlo, whi, rlo, rhi, glo, ghi, blo, bhi;
            up2(aW[k], wlo, whi);
            up2(aR[k], rlo, rhi);
            up2(aG[k], glo, ghi);
            up2(aB[k], blo, bhi);
            float il = 1.0f / wlo, ih = 1.0f / whi;
            int gr = rowBase + r0t + k;
            float* o0 = ob + gr * W_IMG + gc;
            *(float2*)(o0)             = make_float2(fminf(fmaxf(rlo * il, 0.f), 1.f),
                                                     fminf(fmaxf(rhi * ih, 0.f), 1.f));
            *(float2*)(o0 + PLANE)     = make_float2(fminf(fmaxf(glo * il, 0.f), 1.f),
                                                     fminf(fmaxf(ghi * ih, 0.f), 1.f));
            *(float2*)(o0 + 2 * PLANE) = make_float2(fminf(fmaxf(blo * il, 0.f), 1.f),
                                                     fminf(fmaxf(bhi * ih, 0.f), 1.f));
        }
    }
}

extern "C" void kernel_launch(void* const* d_in, const int* in_sizes, int n_in,
                              void* d_out, int out_size)
{
    (void)in_sizes; (void)n_in; (void)out_size;
    const float* x = (const float*)d_in[0];
    float* out = (float*)d_out;

    dim3 block(32, WARPS, 1);
    dim3 grid((W_IMG + OUT_COLS - 1) / OUT_COLS,   // 9 (last tile wraps; duplicate
              W_IMG / TILE_ROWS,                   //    writes are bitwise identical)
              2);                                  // 9*32*2 = 576 = one wave @4/SM
    nlm_kernel<<<grid, block>>>(x, out);
}

// round 11
// speedup vs baseline: 1.0660x; 1.0660x over previous
#include <cuda_runtime.h>

#define MASK  511
#define W_IMG 512
#define PLANE (512 * 512)

#define R_OUT     4                      // out rows per warp
#define WARPS     4
#define TILE_ROWS 16                     // out rows per block
#define OUT_COLS  60                     // out cols per block (lanes 1..30, 2 each)
#define TROWS     30                     // 16 + 2*7 halo
#define TCOLS     76                     // 75 used + 1 pad (even => 8B alignment holds)
#define TPIX      (TROWS * TCOLS)        // 2280
#define FULLM     0xffffffffu

typedef unsigned long long u64;

__device__ __forceinline__ u64 pk(float a, float b) {
    u64 r; asm("mov.b64 %0, {%1, %2};" : "=l"(r) : "f"(a), "f"(b)); return r;
}
__device__ __forceinline__ void up2(u64 v, float& a, float& b) {
    asm("mov.b64 {%0, %1}, %2;" : "=f"(a), "=f"(b) : "l"(v));
}
__device__ __forceinline__ u64 fma2(u64 a, u64 b, u64 c) {
    u64 d; asm("fma.rn.f32x2 %0, %1, %2, %3;" : "=l"(d) : "l"(a), "l"(b), "l"(c)); return d;
}
__device__ __forceinline__ u64 mul2(u64 a, u64 b) {
    u64 d; asm("mul.rn.f32x2 %0, %1, %2;" : "=l"(d) : "l"(a), "l"(b)); return d;
}
__device__ __forceinline__ u64 add2(u64 a, u64 b) {
    u64 d; asm("add.rn.f32x2 %0, %1, %2;" : "=l"(d) : "l"(a), "l"(b)); return d;
}
__device__ __forceinline__ float fsqrt_ap(float x) {
    float r; asm("sqrt.approx.f32 %0, %1;" : "=f"(r) : "f"(x)); return r;
}
// ex2 of the NEGATED input; ptxas folds the neg into the operand modifier
__device__ __forceinline__ float fex2n(float x) {
    float r; asm("ex2.approx.f32 %0, %1;" : "=f"(r) : "f"(-x)); return r;
}

#define NEG1 0xBF800000BF800000ULL               /* {-1.f,-1.f} */
#define YSCL 0.4808983469629878f                 /* log2(e)/3: pre-folded into y */

// One horizontal offset ox, all 11 oy, R_OUT=4 rows.
// shy : pair-aligned shifted-y base (for odd ox it's the ysB shift-by-1 plane).
// x*0 : channel plane + x fetch column (even either parity => aligned LDS.64).
// ODD : accumulation targets cols (cx+1,cx+2) [phase B] vs (cx,cx+1) [phase A].
// The oy loop is intentionally NOT unrolled: keeps the static code footprint
// inside the I$ (the fully-unrolled version is ~56KB and pays the I$-miss tax).
// s-rows are re-read from smem each oy via pointer-increment + const offsets.
template<bool ODD>
__device__ __forceinline__ void process_ox(
    const float* __restrict__ shy,
    const float* __restrict__ xr0, const float* __restrict__ xg0,
    const float* __restrict__ xb0,
    const u64* __restrict__ yreg, int r0t,
    u64* aW, u64* aR, u64* aG, u64* aB)
{
    const float* sp  = shy + r0t * TCOLS;        // shifted-y row base (row r0t+oyi)
    const float* xpr = xr0 + (r0t + 2) * TCOLS;  // x row base (row r0t+2+oyi)
    const float* xpg = xg0 + (r0t + 2) * TCOLS;
    const float* xpb = xb0 + (r0t + 2) * TCOLS;

    #pragma unroll 1
    for (int oyi = 0; oyi < 11; ++oyi) {
        // squared luminance diffs (scaled): rows r0t+oyi .. r0t+oyi+7
        u64 s[8];
        #pragma unroll
        for (int j = 0; j < 8; ++j) {
            u64 sh = *(const u64*)&sp[j * TCOLS];
            u64 d  = fma2(NEG1, sh, yreg[j]);
            s[j]   = mul2(d, d);
        }

        u64 vs = add2(add2(s[0], s[1]), add2(s[2], s[3]));

        #pragma unroll
        for (int k = 0; k < 4; ++k) {
            u64 v5 = add2(vs, s[k + 4]);
            if (k < 3) vs = fma2(NEG1, s[k], v5);        // slide window

            float a, b; up2(v5, a, b);
            float t = a + b;                             // local pair sum
            float d2lo, d2hi;
            if (!ODD) {
                float cm = __shfl_up_sync  (FULLM, t, 1);
                float cp = __shfl_down_sync(FULLM, t, 1);
                float ap = __shfl_down_sync(FULLM, a, 1);
                float bm = __shfl_up_sync  (FULLM, b, 1);
                d2lo = (cm + t) + ap;                    // col cx
                d2hi = (bm + t) + cp;                    // col cx+1
            } else {
                float cp = __shfl_down_sync(FULLM, t, 1);
                float bm = __shfl_up_sync  (FULLM, b, 1);
                float a2 = __shfl_down_sync(FULLM, a, 2);
                d2lo = (bm + t) + cp;                    // col cx+1
                d2hi = (t + cp) + a2;                    // col cx+2
            }
            float wlo = fex2n(fsqrt_ap(d2lo));           // e^(-dist/3)
            float whi = fex2n(fsqrt_ap(d2hi));
            u64  w2   = pk(wlo, whi);
            aW[k] = add2(aW[k], w2);
            aR[k] = fma2(w2, *(const u64*)&xpr[k * TCOLS], aR[k]);
            aG[k] = fma2(w2, *(const u64*)&xpg[k * TCOLS], aG[k]);
            aB[k] = fma2(w2, *(const u64*)&xpb[k * TCOLS], aB[k]);
        }

        sp  += TCOLS;
        xpr += TCOLS; xpg += TCOLS; xpb += TCOLS;
    }
}

__global__ __launch_bounds__(32 * WARPS, 4)
void nlm_kernel(const float* __restrict__ x, float* __restrict__ out)
{
    __shared__ __align__(16) float smem[5 * TPIX];   // ys | ysB | xr | xg | xb
    float* ys  = smem;
    float* ysB = smem + TPIX;                        // ysB[r][c] = ys[r][c+1]
    float* xr  = smem + 2 * TPIX;
    float* xg  = smem + 3 * TPIX;
    float* xb  = smem + 4 * TPIX;

    const int lane = threadIdx.x;
    const int warp = threadIdx.y;
    const int tid  = warp * 32 + lane;

    const int n       = blockIdx.z;
    const int rowBase = blockIdx.y * TILE_ROWS;
    const int colBase = blockIdx.x * OUT_COLS;
    const int rowTop  = rowBase - 7 + 512;
    const int colLeft = colBase - 8 + 512;

    const float* xbase = x + (size_t)n * 3 * PLANE;

    for (int idx = tid; idx < TPIX; idx += 32 * WARPS) {
        int r  = idx / TCOLS;
        int c  = idx - r * TCOLS;
        int gy = (rowTop + r) & MASK;
        int gx = (colLeft + c) & MASK;
        const float* p = xbase + gy * W_IMG + gx;
        float rv = p[0];
        float gv = p[PLANE];
        float bv = p[2 * PLANE];
        float rc = fminf(fmaxf(rv, 0.f), 1.f);
        float gc = fminf(fmaxf(gv, 0.f), 1.f);
        float bc = fminf(fmaxf(bv, 0.f), 1.f);
        // luminance pre-scaled by log2(e)/3 so the weight is ex2(-sqrt(d2))
        float yv = (0.299f * YSCL) * rc + (0.587f * YSCL) * gc + (0.114f * YSCL) * bc;
        xr[idx] = rv; xg[idx] = gv; xb[idx] = bv; ys[idx] = yv;
        if (c) ysB[idx - 1] = yv;
    }
    __syncthreads();

    const int r0t = warp * R_OUT;          // warp's out-row start (tile row +7)
    const int cx  = 6 + 2 * lane;          // own pair: tile cols (cx, cx+1)

    // own pairs (scaled), template rows r0t+5 .. r0t+12
    u64 yreg[8];
    #pragma unroll
    for (int j = 0; j < 8; ++j)
        yreg[j] = *(const u64*)&ys[(r0t + 5 + j) * TCOLS + cx];

    u64 aW[4], aR[4], aG[4], aB[4];        // single set; starts in phase-B layout
    #pragma unroll
    for (int k = 0; k < 4; ++k) { aW[k] = 0ULL; aR[k] = 0ULL; aG[k] = 0ULL; aB[k] = 0ULL; }

    // ---- odd offsets first, phase-B layout: cols (cx+1, cx+2) ----
    #pragma unroll 1
    for (int ox = -5; ox <= 5; ox += 2)
        process_ox<true>(ysB + cx + ox - 1,
                         xr + cx + ox + 1, xg + cx + ox + 1, xb + cx + ox + 1,
                         yreg, r0t, aW, aR, aG, aB);

    // ---- re-align phase B -> phase A: lane L's lo(cx) = lane L-1's hi ----
    #pragma unroll
    for (int k = 0; k < 4; ++k) {
        float lo, hi;
        up2(aW[k], lo, hi); aW[k] = pk(__shfl_up_sync(FULLM, hi, 1), lo);
        up2(aR[k], lo, hi); aR[k] = pk(__shfl_up_sync(FULLM, hi, 1), lo);
        up2(aG[k], lo, hi); aG[k] = pk(__shfl_up_sync(FULLM, hi, 1), lo);
        up2(aB[k], lo, hi); aB[k] = pk(__shfl_up_sync(FULLM, hi, 1), lo);
    }

    // ---- even offsets, phase-A layout: cols (cx, cx+1) ----
    #pragma unroll 1
    for (int ox = -4; ox <= 4; ox += 2)
        process_ox<false>(ys + cx + ox,
                          xr + cx + ox, xg + cx + ox, xb + cx + ox,
                          yreg, r0t, aW, aR, aG, aB);

    // ---- write output (lanes 1..30 own 60 output cols) ----
    if (lane >= 1 && lane <= 30) {
        int gc = (colBase + 2 * (lane - 1)) & MASK;   // even; pair contiguous
        float* ob = out + (size_t)n * 3 * PLANE;
        #pragma unroll
        for (int k = 0; k < 4; ++k) {
            float wlo, whi, rlo, rhi, glo, ghi, blo, bhi;
            up2(aW[k], wlo, whi);
            up2(aR[k], rlo, rhi);
            up2(aG[k], glo, ghi);
            up2(aB[k], blo, bhi);
            float il = 1.0f / wlo, ih = 1.0f / whi;
            int gr = rowBase + r0t + k;
            float* o0 = ob + gr * W_IMG + gc;
            *(float2*)(o0)             = make_float2(fminf(fmaxf(rlo * il, 0.f), 1.f),
                                                     fminf(fmaxf(rhi * ih, 0.f), 1.f));
            *(float2*)(o0 + PLANE)     = make_float2(fminf(fmaxf(glo * il, 0.f), 1.f),
                                                     fminf(fmaxf(ghi * ih, 0.f), 1.f));
            *(float2*)(o0 + 2 * PLANE) = make_float2(fminf(fmaxf(blo * il, 0.f), 1.f),
                                                     fminf(fmaxf(bhi * ih, 0.f), 1.f));
        }
    }
}

extern "C" void kernel_launch(void* const* d_in, const int* in_sizes, int n_in,
                              void* d_out, int out_size)
{
    (void)in_sizes; (void)n_in; (void)out_size;
    const float* x = (const float*)d_in[0];
    float* out = (float*)d_out;

    dim3 block(32, WARPS, 1);
    dim3 grid((W_IMG + OUT_COLS - 1) / OUT_COLS,   // 9 (last tile wraps; duplicate
              W_IMG / TILE_ROWS,                   //    writes are bitwise identical)
              2);                                  // 9*32*2 = 576 = one wave @4/SM
    nlm_kernel<<<grid, block>>>(x, out);
}

// round 12
// speedup vs baseline: 1.1195x; 1.0502x over previous
#include <cuda_runtime.h>

#define MASK  511
#define W_IMG 512
#define PLANE (512 * 512)

#define R_OUT     4                      // out rows per warp
#define WARPS     4
#define TILE_ROWS 16                     // out rows per block
#define OUT_COLS  60                     // out cols per block (lanes 1..30, 2 each)
#define TROWS     30                     // 16 + 2*7 halo
#define TCOLS     76                     // 75 used + 1 pad (even => 8B alignment holds)
#define TPIX      (TROWS * TCOLS)        // 2280
#define FULLM     0xffffffffu

typedef unsigned long long u64;

__device__ __forceinline__ u64 pk(float a, float b) {
    u64 r; asm("mov.b64 %0, {%1, %2};" : "=l"(r) : "f"(a), "f"(b)); return r;
}
__device__ __forceinline__ void up2(u64 v, float& a, float& b) {
    asm("mov.b64 {%0, %1}, %2;" : "=f"(a), "=f"(b) : "l"(v));
}
__device__ __forceinline__ u64 fma2(u64 a, u64 b, u64 c) {
    u64 d; asm("fma.rn.f32x2 %0, %1, %2, %3;" : "=l"(d) : "l"(a), "l"(b), "l"(c)); return d;
}
__device__ __forceinline__ u64 mul2(u64 a, u64 b) {
    u64 d; asm("mul.rn.f32x2 %0, %1, %2;" : "=l"(d) : "l"(a), "l"(b)); return d;
}
__device__ __forceinline__ u64 add2(u64 a, u64 b) {
    u64 d; asm("add.rn.f32x2 %0, %1, %2;" : "=l"(d) : "l"(a), "l"(b)); return d;
}
__device__ __forceinline__ float fsqrt_ap(float x) {
    float r; asm("sqrt.approx.f32 %0, %1;" : "=f"(r) : "f"(x)); return r;
}
// ex2 of the NEGATED input; ptxas folds the neg into the operand modifier
__device__ __forceinline__ float fex2n(float x) {
    float r; asm("ex2.approx.f32 %0, %1;" : "=f"(r) : "f"(-x)); return r;
}

#define NEG1 0xBF800000BF800000ULL               /* {-1.f,-1.f} */
#define YSCL 0.4808983469629878f                 /* log2(e)/3: pre-folded into y */

// One horizontal offset ox, all 11 oy, R_OUT=4 rows.
// shy : pair-aligned shifted-y base (for odd ox it's the ysB shift-by-1 plane).
// x*0 : channel plane + x fetch column (even either parity => aligned LDS.64).
// ODD : accumulation targets cols (cx+1,cx+2) [phase B] vs (cx,cx+1) [phase A].
// oy loop unrolled by 2: consecutive oy share 7/8 shifted-y rows and 3/4 x
// rows at IDENTICAL smem addresses -> ptxas CSEs the duplicate LDS, and the
// two bodies give 2x ILP across the SHFL->MUFU->MUFU chains. Body stays small
// enough (~7KB/instantiation) to live in the I$.
template<bool ODD>
__device__ __forceinline__ void process_ox(
    const float* __restrict__ shy,
    const float* __restrict__ xr0, const float* __restrict__ xg0,
    const float* __restrict__ xb0,
    const u64* __restrict__ yreg, int r0t,
    u64* aW, u64* aR, u64* aG, u64* aB)
{
    const float* sp  = shy + r0t * TCOLS;        // shifted-y row base (row r0t+oyi)
    const float* xpr = xr0 + (r0t + 2) * TCOLS;  // x row base (row r0t+2+oyi)
    const float* xpg = xg0 + (r0t + 2) * TCOLS;
    const float* xpb = xb0 + (r0t + 2) * TCOLS;

    #pragma unroll 2
    for (int oyi = 0; oyi < 11; ++oyi) {
        // squared luminance diffs (scaled): rows r0t+oyi .. r0t+oyi+7
        u64 s[8];
        #pragma unroll
        for (int j = 0; j < 8; ++j) {
            u64 sh = *(const u64*)&sp[j * TCOLS];
            u64 d  = fma2(NEG1, sh, yreg[j]);
            s[j]   = mul2(d, d);
        }

        u64 vs = add2(add2(s[0], s[1]), add2(s[2], s[3]));

        #pragma unroll
        for (int k = 0; k < 4; ++k) {
            u64 v5 = add2(vs, s[k + 4]);
            if (k < 3) vs = fma2(NEG1, s[k], v5);        // slide window

            float a, b; up2(v5, a, b);
            float t = a + b;                             // local pair sum
            float d2lo, d2hi;
            if (!ODD) {
                float cm = __shfl_up_sync  (FULLM, t, 1);
                float cp = __shfl_down_sync(FULLM, t, 1);
                float ap = __shfl_down_sync(FULLM, a, 1);
                float bm = __shfl_up_sync  (FULLM, b, 1);
                d2lo = (cm + t) + ap;                    // col cx
                d2hi = (bm + t) + cp;                    // col cx+1
            } else {
                float cp = __shfl_down_sync(FULLM, t, 1);
                float bm = __shfl_up_sync  (FULLM, b, 1);
                float a2 = __shfl_down_sync(FULLM, a, 2);
                d2lo = (bm + t) + cp;                    // col cx+1
                d2hi = (t + cp) + a2;                    // col cx+2
            }
            float wlo = fex2n(fsqrt_ap(d2lo));           // e^(-dist/3)
            float whi = fex2n(fsqrt_ap(d2hi));
            u64  w2   = pk(wlo, whi);
            aW[k] = add2(aW[k], w2);
            aR[k] = fma2(w2, *(const u64*)&xpr[k * TCOLS], aR[k]);
            aG[k] = fma2(w2, *(const u64*)&xpg[k * TCOLS], aG[k]);
            aB[k] = fma2(w2, *(const u64*)&xpb[k * TCOLS], aB[k]);
        }

        sp  += TCOLS;
        xpr += TCOLS; xpg += TCOLS; xpb += TCOLS;
    }
}

__global__ __launch_bounds__(32 * WARPS, 4)
void nlm_kernel(const float* __restrict__ x, float* __restrict__ out)
{
    __shared__ __align__(16) float smem[5 * TPIX];   // ys | ysB | xr | xg | xb
    float* ys  = smem;
    float* ysB = smem + TPIX;                        // ysB[r][c] = ys[r][c+1]
    float* xr  = smem + 2 * TPIX;
    float* xg  = smem + 3 * TPIX;
    float* xb  = smem + 4 * TPIX;

    const int lane = threadIdx.x;
    const int warp = threadIdx.y;
    const int tid  = warp * 32 + lane;

    const int n       = blockIdx.z;
    const int rowBase = blockIdx.y * TILE_ROWS;
    const int colBase = blockIdx.x * OUT_COLS;
    const int rowTop  = rowBase - 7 + 512;
    const int colLeft = colBase - 8 + 512;

    const float* xbase = x + (size_t)n * 3 * PLANE;

    for (int idx = tid; idx < TPIX; idx += 32 * WARPS) {
        int r  = idx / TCOLS;
        int c  = idx - r * TCOLS;
        int gy = (rowTop + r) & MASK;
        int gx = (colLeft + c) & MASK;
        const float* p = xbase + gy * W_IMG + gx;
        float rv = p[0];
        float gv = p[PLANE];
        float bv = p[2 * PLANE];
        float rc = fminf(fmaxf(rv, 0.f), 1.f);
        float gc = fminf(fmaxf(gv, 0.f), 1.f);
        float bc = fminf(fmaxf(bv, 0.f), 1.f);
        // luminance pre-scaled by log2(e)/3 so the weight is ex2(-sqrt(d2))
        float yv = (0.299f * YSCL) * rc + (0.587f * YSCL) * gc + (0.114f * YSCL) * bc;
        xr[idx] = rv; xg[idx] = gv; xb[idx] = bv; ys[idx] = yv;
        if (c) ysB[idx - 1] = yv;
    }
    __syncthreads();

    const int r0t = warp * R_OUT;          // warp's out-row start (tile row +7)
    const int cx  = 6 + 2 * lane;          // own pair: tile cols (cx, cx+1)

    // own pairs (scaled), template rows r0t+5 .. r0t+12
    u64 yreg[8];
    #pragma unroll
    for (int j = 0; j < 8; ++j)
        yreg[j] = *(const u64*)&ys[(r0t + 5 + j) * TCOLS + cx];

    u64 aW[4], aR[4], aG[4], aB[4];        // single set; starts in phase-B layout
    #pragma unroll
    for (int k = 0; k < 4; ++k) { aW[k] = 0ULL; aR[k] = 0ULL; aG[k] = 0ULL; aB[k] = 0ULL; }

    // ---- odd offsets first, phase-B layout: cols (cx+1, cx+2) ----
    #pragma unroll 1
    for (int ox = -5; ox <= 5; ox += 2)
        process_ox<true>(ysB + cx + ox - 1,
                         xr + cx + ox + 1, xg + cx + ox + 1, xb + cx + ox + 1,
                         yreg, r0t, aW, aR, aG, aB);

    // ---- re-align phase B -> phase A: lane L's lo(cx) = lane L-1's hi ----
    #pragma unroll
    for (int k = 0; k < 4; ++k) {
        float lo, hi;
        up2(aW[k], lo, hi); aW[k] = pk(__shfl_up_sync(FULLM, hi, 1), lo);
        up2(aR[k], lo, hi); aR[k] = pk(__shfl_up_sync(FULLM, hi, 1), lo);
        up2(aG[k], lo, hi); aG[k] = pk(__shfl_up_sync(FULLM, hi, 1), lo);
        up2(aB[k], lo, hi); aB[k] = pk(__shfl_up_sync(FULLM, hi, 1), lo);
    }

    // ---- even offsets, phase-A layout: cols (cx, cx+1) ----
    #pragma unroll 1
    for (int ox = -4; ox <= 4; ox += 2)
        process_ox<false>(ys + cx + ox,
                          xr + cx + ox, xg + cx + ox, xb + cx + ox,
                          yreg, r0t, aW, aR, aG, aB);

    // ---- write output (lanes 1..30 own 60 output cols) ----
    if (lane >= 1 && lane <= 30) {
        int gc = (colBase + 2 * (lane - 1)) & MASK;   // even; pair contiguous
        float* ob = out + (size_t)n * 3 * PLANE;
        #pragma unroll
        for (int k = 0; k < 4; ++k) {
            float wlo, whi, rlo, rhi, glo, ghi, blo, bhi;
            up2(aW[k], wlo, whi);
            up2(aR[k], rlo, rhi);
            up2(aG[k], glo, ghi);
            up2(aB[k], blo, bhi);
            float il = 1.0f / wlo, ih = 1.0f / whi;
            int gr = rowBase + r0t + k;
            float* o0 = ob + gr * W_IMG + gc;
            *(float2*)(o0)             = make_float2(fminf(fmaxf(rlo * il, 0.f), 1.f),
                                                     fminf(fmaxf(rhi * ih, 0.f), 1.f));
            *(float2*)(o0 + PLANE)     = make_float2(fminf(fmaxf(glo * il, 0.f), 1.f),
                                                     fminf(fmaxf(ghi * ih, 0.f), 1.f));
            *(float2*)(o0 + 2 * PLANE) = make_float2(fminf(fmaxf(blo * il, 0.f), 1.f),
                                                     fminf(fmaxf(bhi * ih, 0.f), 1.f));
        }
    }
}

extern "C" void kernel_launch(void* const* d_in, const int* in_sizes, int n_in,
                              void* d_out, int out_size)
{
    (void)in_sizes; (void)n_in; (void)out_size;
    const float* x = (const float*)d_in[0];
    float* out = (float*)d_out;

    dim3 block(32, WARPS, 1);
    dim3 grid((W_IMG + OUT_COLS - 1) / OUT_COLS,   // 9 (last tile wraps; duplicate
              W_IMG / TILE_ROWS,                   //    writes are bitwise identical)
              2);                                  // 9*32*2 = 576 = one wave @4/SM
    nlm_kernel<<<grid, block>>>(x, out);
}

// round 13
// speedup vs baseline: 1.1449x; 1.0227x over previous
#include <cuda_runtime.h>

#define MASK  511
#define W_IMG 512
#define PLANE (512 * 512)

#define R_OUT     4                      // out rows per warp
#define WARPS     4
#define TILE_ROWS 16                     // out rows per block
#define OUT_COLS  60                     // out cols per block (lanes 1..30, 2 each)
#define TROWS     30                     // 16 + 2*7 halo
#define TCOLS     76                     // 75 used + 1 pad (even => 8B alignment holds)
#define TPIX      (TROWS * TCOLS)        // 2280
#define FULLM     0xffffffffu

typedef unsigned long long u64;

__device__ __forceinline__ u64 pk(float a, float b) {
    u64 r; asm("mov.b64 %0, {%1, %2};" : "=l"(r) : "f"(a), "f"(b)); return r;
}
__device__ __forceinline__ void up2(u64 v, float& a, float& b) {
    asm("mov.b64 {%0, %1}, %2;" : "=f"(a), "=f"(b) : "l"(v));
}
__device__ __forceinline__ u64 fma2(u64 a, u64 b, u64 c) {
    u64 d; asm("fma.rn.f32x2 %0, %1, %2, %3;" : "=l"(d) : "l"(a), "l"(b), "l"(c)); return d;
}
__device__ __forceinline__ u64 mul2(u64 a, u64 b) {
    u64 d; asm("mul.rn.f32x2 %0, %1, %2;" : "=l"(d) : "l"(a), "l"(b)); return d;
}
__device__ __forceinline__ u64 add2(u64 a, u64 b) {
    u64 d; asm("add.rn.f32x2 %0, %1, %2;" : "=l"(d) : "l"(a), "l"(b)); return d;
}
__device__ __forceinline__ float fsqrt_ap(float x) {
    float r; asm("sqrt.approx.f32 %0, %1;" : "=f"(r) : "f"(x)); return r;
}
// ex2 of the NEGATED input; ptxas folds the neg into the operand modifier
__device__ __forceinline__ float fex2n(float x) {
    float r; asm("ex2.approx.f32 %0, %1;" : "=f"(r) : "f"(-x)); return r;
}

#define NEG1 0xBF800000BF800000ULL               /* {-1.f,-1.f} */
#define YSCL 0.4808983469629878f                 /* log2(e)/3: pre-folded into y */

// One horizontal offset ox, all 11 oy, R_OUT=4 rows.
// sp  : single running pointer at the shifted-y row (row r0t+oyi). The x
//       channel rows live at COMPILE-TIME-CONSTANT deltas from sp:
//         odd : shy = ysB + cx+ox-1, x fetch col = cx+ox+1  -> base delta
//               (xr - ysB) + 2 = TPIX + 2
//         even: shy = ys + cx+ox,   x fetch col = cx+ox     -> delta 2*TPIX
//       plus +2*TCOLS because x rows trail y rows by 2.  One IADD per oy
//       instead of four; all streams use LDS immediate offsets.
// ODD : accumulation targets cols (cx+1,cx+2) [phase B] vs (cx,cx+1) [phase A].
// oy loop unrolled by 3: consecutive oy share 7/8 shifted-y rows and 3/4 x
// rows at IDENTICAL smem addresses -> ptxas CSEs the duplicate LDS; 3 bodies
// give ILP across the SHFL->MUFU->MUFU chains. Body stays far from the I$ cliff.
template<bool ODD>
__device__ __forceinline__ void process_ox(
    const float* __restrict__ shy,
    const u64* __restrict__ yreg, int r0t,
    u64* aW, u64* aR, u64* aG, u64* aB)
{
    constexpr int XRO = (ODD ? (TPIX + 2) : (2 * TPIX)) + 2 * TCOLS;
    constexpr int XGO = XRO + TPIX;
    constexpr int XBO = XRO + 2 * TPIX;

    const float* sp = shy + r0t * TCOLS;

    #pragma unroll 3
    for (int oyi = 0; oyi < 11; ++oyi) {
        // squared luminance diffs (scaled): rows r0t+oyi .. r0t+oyi+7
        u64 s[8];
        #pragma unroll
        for (int j = 0; j < 8; ++j) {
            u64 sh = *(const u64*)&sp[j * TCOLS];
            u64 d  = fma2(NEG1, sh, yreg[j]);
            s[j]   = mul2(d, d);
        }

        u64 vs = add2(add2(s[0], s[1]), add2(s[2], s[3]));

        #pragma unroll
        for (int k = 0; k < 4; ++k) {
            u64 v5 = add2(vs, s[k + 4]);
            if (k < 3) vs = fma2(NEG1, s[k], v5);        // slide window

            float a, b; up2(v5, a, b);
            float t = a + b;                             // local pair sum
            float d2lo, d2hi;
            if (!ODD) {
                float cm = __shfl_up_sync  (FULLM, t, 1);
                float cp = __shfl_down_sync(FULLM, t, 1);
                float ap = __shfl_down_sync(FULLM, a, 1);
                float bm = __shfl_up_sync  (FULLM, b, 1);
                d2lo = (cm + t) + ap;                    // col cx
                d2hi = (bm + t) + cp;                    // col cx+1
            } else {
                float cp = __shfl_down_sync(FULLM, t, 1);
                float bm = __shfl_up_sync  (FULLM, b, 1);
                float a2 = __shfl_down_sync(FULLM, a, 2);
                float u  = t + cp;                       // shared partial
                d2lo = bm + u;                           // col cx+1
                d2hi = u + a2;                           // col cx+2
            }
            float wlo = fex2n(fsqrt_ap(d2lo));           // e^(-dist/3)
            float whi = fex2n(fsqrt_ap(d2hi));
            u64  w2   = pk(wlo, whi);
            aW[k] = add2(aW[k], w2);
            aR[k] = fma2(w2, *(const u64*)&sp[XRO + k * TCOLS], aR[k]);
            aG[k] = fma2(w2, *(const u64*)&sp[XGO + k * TCOLS], aG[k]);
            aB[k] = fma2(w2, *(const u64*)&sp[XBO + k * TCOLS], aB[k]);
        }

        sp += TCOLS;
    }
}

__global__ __launch_bounds__(32 * WARPS, 4)
void nlm_kernel(const float* __restrict__ x, float* __restrict__ out)
{
    __shared__ __align__(16) float smem[5 * TPIX];   // ys | ysB | xr | xg | xb
    float* ys  = smem;
    float* ysB = smem + TPIX;                        // ysB[r][c] = ys[r][c+1]
    float* xr  = smem + 2 * TPIX;
    float* xg  = smem + 3 * TPIX;
    float* xb  = smem + 4 * TPIX;

    const int lane = threadIdx.x;
    const int warp = threadIdx.y;
    const int tid  = warp * 32 + lane;

    const int n       = blockIdx.z;
    const int rowBase = blockIdx.y * TILE_ROWS;
    const int colBase = blockIdx.x * OUT_COLS;
    const int rowTop  = rowBase - 7 + 512;
    const int colLeft = colBase - 8 + 512;

    const float* xbase = x + (size_t)n * 3 * PLANE;

    for (int idx = tid; idx < TPIX; idx += 32 * WARPS) {
        int r  = idx / TCOLS;
        int c  = idx - r * TCOLS;
        int gy = (rowTop + r) & MASK;
        int gx = (colLeft + c) & MASK;
        const float* p = xbase + gy * W_IMG + gx;
        float rv = p[0];
        float gv = p[PLANE];
        float bv = p[2 * PLANE];
        float rc = fminf(fmaxf(rv, 0.f), 1.f);
        float gc = fminf(fmaxf(gv, 0.f), 1.f);
        float bc = fminf(fmaxf(bv, 0.f), 1.f);
        // luminance pre-scaled by log2(e)/3 so the weight is ex2(-sqrt(d2))
        float yv = (0.299f * YSCL) * rc + (0.587f * YSCL) * gc + (0.114f * YSCL) * bc;
        xr[idx] = rv; xg[idx] = gv; xb[idx] = bv; ys[idx] = yv;
        if (c) ysB[idx - 1] = yv;
    }
    __syncthreads();

    const int r0t = warp * R_OUT;          // warp's out-row start (tile row +7)
    const int cx  = 6 + 2 * lane;          // own pair: tile cols (cx, cx+1)

    // own pairs (scaled), template rows r0t+5 .. r0t+12
    u64 yreg[8];
    #pragma unroll
    for (int j = 0; j < 8; ++j)
        yreg[j] = *(const u64*)&ys[(r0t + 5 + j) * TCOLS + cx];

    u64 aW[4], aR[4], aG[4], aB[4];        // single set; starts in phase-B layout
    #pragma unroll
    for (int k = 0; k < 4; ++k) { aW[k] = 0ULL; aR[k] = 0ULL; aG[k] = 0ULL; aB[k] = 0ULL; }

    // ---- odd offsets first, phase-B layout: cols (cx+1, cx+2) ----
    #pragma unroll 1
    for (int ox = -5; ox <= 5; ox += 2)
        process_ox<true>(ysB + cx + ox - 1, yreg, r0t, aW, aR, aG, aB);

    // ---- re-align phase B -> phase A: lane L's lo(cx) = lane L-1's hi ----
    #pragma unroll
    for (int k = 0; k < 4; ++k) {
        float lo, hi;
        up2(aW[k], lo, hi); aW[k] = pk(__shfl_up_sync(FULLM, hi, 1), lo);
        up2(aR[k], lo, hi); aR[k] = pk(__shfl_up_sync(FULLM, hi, 1), lo);
        up2(aG[k], lo, hi); aG[k] = pk(__shfl_up_sync(FULLM, hi, 1), lo);
        up2(aB[k], lo, hi); aB[k] = pk(__shfl_up_sync(FULLM, hi, 1), lo);
    }

    // ---- even offsets, phase-A layout: cols (cx, cx+1) ----
    #pragma unroll 1
    for (int ox = -4; ox <= 4; ox += 2)
        process_ox<false>(ys + cx + ox, yreg, r0t, aW, aR, aG, aB);

    // ---- write output (lanes 1..30 own 60 output cols) ----
    if (lane >= 1 && lane <= 30) {
        int gc = (colBase + 2 * (lane - 1)) & MASK;   // even; pair contiguous
        float* ob = out + (size_t)n * 3 * PLANE;
        #pragma unroll
        for (int k = 0; k < 4; ++k) {
            float wlo, whi, rlo, rhi, glo, ghi, blo, bhi;
            up2(aW[k], wlo, whi);
            up2(aR[k], rlo, rhi);
            up2(aG[k], glo, ghi);
            up2(aB[k], blo, bhi);
            float il = 1.0f / wlo, ih = 1.0f / whi;
            int gr = rowBase + r0t + k;
            float* o0 = ob + gr * W_IMG + gc;
            *(float2*)(o0)             = make_float2(fminf(fmaxf(rlo * il, 0.f), 1.f),
                                                     fminf(fmaxf(rhi * ih, 0.f), 1.f));
            *(float2*)(o0 + PLANE)     = make_float2(fminf(fmaxf(glo * il, 0.f), 1.f),
                                                     fminf(fmaxf(ghi * ih, 0.f), 1.f));
            *(float2*)(o0 + 2 * PLANE) = make_float2(fminf(fmaxf(blo * il, 0.f), 1.f),
                                                     fminf(fmaxf(bhi * ih, 0.f), 1.f));
        }
    }
}

extern "C" void kernel_launch(void* const* d_in, const int* in_sizes, int n_in,
                              void* d_out, int out_size)
{
    (void)in_sizes; (void)n_in; (void)out_size;
    const float* x = (const float*)d_in[0];
    float* out = (float*)d_out;

    dim3 block(32, WARPS, 1);
    dim3 grid((W_IMG + OUT_COLS - 1) / OUT_COLS,   // 9 (last tile wraps; duplicate
              W_IMG / TILE_ROWS,                   //    writes are bitwise identical)
              2);                                  // 9*32*2 = 576 = one wave @4/SM
    nlm_kernel<<<grid, block>>>(x, out);
}

// round 14
// speedup vs baseline: 1.1709x; 1.0227x over previous
#include <cuda_runtime.h>

#define MASK  511
#define W_IMG 512
#define PLANE (512 * 512)

#define R_OUT     4                      // out rows per warp
#define WARPS     4
#define TILE_ROWS 16                     // out rows per block
#define OUT_COLS  60                     // out cols per block (lanes 1..30, 2 each)
#define TROWS     30                     // 16 + 2*7 halo
#define TCOLS     76                     // 75 used + 1 pad (even => 8B alignment holds)
#define TPIX      (TROWS * TCOLS)        // 2280
#define FULLM     0xffffffffu

typedef unsigned long long u64;

__device__ __forceinline__ u64 pk(float a, float b) {
    u64 r; asm("mov.b64 %0, {%1, %2};" : "=l"(r) : "f"(a), "f"(b)); return r;
}
__device__ __forceinline__ void up2(u64 v, float& a, float& b) {
    asm("mov.b64 {%0, %1}, %2;" : "=f"(a), "=f"(b) : "l"(v));
}
__device__ __forceinline__ u64 fma2(u64 a, u64 b, u64 c) {
    u64 d; asm("fma.rn.f32x2 %0, %1, %2, %3;" : "=l"(d) : "l"(a), "l"(b), "l"(c)); return d;
}
__device__ __forceinline__ u64 mul2(u64 a, u64 b) {
    u64 d; asm("mul.rn.f32x2 %0, %1, %2;" : "=l"(d) : "l"(a), "l"(b)); return d;
}
__device__ __forceinline__ u64 add2(u64 a, u64 b) {
    u64 d; asm("add.rn.f32x2 %0, %1, %2;" : "=l"(d) : "l"(a), "l"(b)); return d;
}
__device__ __forceinline__ float fsqrt_ap(float x) {
    float r; asm("sqrt.approx.f32 %0, %1;" : "=f"(r) : "f"(x)); return r;
}
// ex2 of the NEGATED input; ptxas folds the neg into the operand modifier
__device__ __forceinline__ float fex2n(float x) {
    float r; asm("ex2.approx.f32 %0, %1;" : "=f"(r) : "f"(-x)); return r;
}

#define NEG1 0xBF800000BF800000ULL               /* {-1.f,-1.f} */
#define YSCL 0.4808983469629878f                 /* log2(e)/3: pre-folded into y */

// One horizontal offset ox, all 11 oy, R_OUT=4 rows.
// sp  : single running pointer at the shifted-y row (row r0t+oyi). The x
//       channel rows live at COMPILE-TIME-CONSTANT deltas from sp:
//         odd : shy = ysB + cx+ox-1, x fetch col = cx+ox+1  -> base delta
//               (xr - ysB) + 2 = TPIX + 2
//         even: shy = ys + cx+ox,   x fetch col = cx+ox     -> delta 2*TPIX
//       plus +2*TCOLS because x rows trail y rows by 2.  One IADD per oy
//       instead of four; all streams use LDS immediate offsets.
// ODD : accumulation targets cols (cx+1,cx+2) [phase B] vs (cx,cx+1) [phase A].
// oy loop unrolled by 3: consecutive oy share 7/8 shifted-y rows and 3/4 x
// rows at IDENTICAL smem addresses -> ptxas CSEs the duplicate LDS; 3 bodies
// give ILP across the SHFL->MUFU->MUFU chains. Body stays far from the I$ cliff.
template<bool ODD>
__device__ __forceinline__ void process_ox(
    const float* __restrict__ shy,
    const u64* __restrict__ yreg, int r0t,
    u64* aW, u64* aR, u64* aG, u64* aB)
{
    constexpr int XRO = (ODD ? (TPIX + 2) : (2 * TPIX)) + 2 * TCOLS;
    constexpr int XGO = XRO + TPIX;
    constexpr int XBO = XRO + 2 * TPIX;

    const float* sp = shy + r0t * TCOLS;

    #pragma unroll 3
    for (int oyi = 0; oyi < 11; ++oyi) {
        // squared luminance diffs (scaled): rows r0t+oyi .. r0t+oyi+7
        u64 s[8];
        #pragma unroll
        for (int j = 0; j < 8; ++j) {
            u64 sh = *(const u64*)&sp[j * TCOLS];
            u64 d  = fma2(NEG1, sh, yreg[j]);
            s[j]   = mul2(d, d);
        }

        u64 vs = add2(add2(s[0], s[1]), add2(s[2], s[3]));

        #pragma unroll
        for (int k = 0; k < 4; ++k) {
            u64 v5 = add2(vs, s[k + 4]);
            if (k < 3) vs = fma2(NEG1, s[k], v5);        // slide window

            float a, b; up2(v5, a, b);
            float t = a + b;                             // local pair sum
            float d2lo, d2hi;
            if (!ODD) {
                float cm = __shfl_up_sync  (FULLM, t, 1);
                float cp = __shfl_down_sync(FULLM, t, 1);
                float ap = __shfl_down_sync(FULLM, a, 1);
                float bm = __shfl_up_sync  (FULLM, b, 1);
                d2lo = (cm + t) + ap;                    // col cx
                d2hi = (bm + t) + cp;                    // col cx+1
            } else {
                float cp = __shfl_down_sync(FULLM, t, 1);
                float bm = __shfl_up_sync  (FULLM, b, 1);
                float a2 = __shfl_down_sync(FULLM, a, 2);
                float u  = t + cp;                       // shared partial
                d2lo = bm + u;                           // col cx+1
                d2hi = u + a2;                           // col cx+2
            }
            float wlo = fex2n(fsqrt_ap(d2lo));           // e^(-dist/3)
            float whi = fex2n(fsqrt_ap(d2hi));
            u64  w2   = pk(wlo, whi);
            aW[k] = add2(aW[k], w2);
            aR[k] = fma2(w2, *(const u64*)&sp[XRO + k * TCOLS], aR[k]);
            aG[k] = fma2(w2, *(const u64*)&sp[XGO + k * TCOLS], aG[k]);
            aB[k] = fma2(w2, *(const u64*)&sp[XBO + k * TCOLS], aB[k]);
        }

        sp += TCOLS;
    }
}

__global__ __launch_bounds__(32 * WARPS, 4)
void nlm_kernel(const float* __restrict__ x, float* __restrict__ out)
{
    __shared__ __align__(16) float smem[5 * TPIX];   // ys | ysB | xr | xg | xb
    float* ys  = smem;
    float* ysB = smem + TPIX;                        // ysB[r][c] = ys[r][c+1]
    float* xr  = smem + 2 * TPIX;
    float* xg  = smem + 3 * TPIX;
    float* xb  = smem + 4 * TPIX;

    const int lane = threadIdx.x;
    const int warp = threadIdx.y;
    const int tid  = warp * 32 + lane;

    const int n       = blockIdx.z;
    const int rowBase = blockIdx.y * TILE_ROWS;
    const int colBase = blockIdx.x * OUT_COLS;
    const int rowTop  = rowBase - 7 + 512;
    const int colLeft = colBase - 8 + 512;

    const float* xbase = x + (size_t)n * 3 * PLANE;

    for (int idx = tid; idx < TPIX; idx += 32 * WARPS) {
        int r  = idx / TCOLS;
        int c  = idx - r * TCOLS;
        int gy = (rowTop + r) & MASK;
        int gx = (colLeft + c) & MASK;
        const float* p = xbase + gy * W_IMG + gx;
        float rv = p[0];
        float gv = p[PLANE];
        float bv = p[2 * PLANE];
        float rc = fminf(fmaxf(rv, 0.f), 1.f);
        float gc = fminf(fmaxf(gv, 0.f), 1.f);
        float bc = fminf(fmaxf(bv, 0.f), 1.f);
        // luminance pre-scaled by log2(e)/3 so the weight is ex2(-sqrt(d2))
        float yv = (0.299f * YSCL) * rc + (0.587f * YSCL) * gc + (0.114f * YSCL) * bc;
        xr[idx] = rv; xg[idx] = gv; xb[idx] = bv; ys[idx] = yv;
        if (c) ysB[idx - 1] = yv;
    }
    __syncthreads();

    const int r0t = warp * R_OUT;          // warp's out-row start (tile row +7)
    const int cx  = 6 + 2 * lane;          // own pair: tile cols (cx, cx+1)

    // own pairs (scaled), template rows r0t+5 .. r0t+12
    u64 yreg[8];
    #pragma unroll
    for (int j = 0; j < 8; ++j)
        yreg[j] = *(const u64*)&ys[(r0t + 5 + j) * TCOLS + cx];

    u64 aW[4], aR[4], aG[4], aB[4];        // single set; starts in phase-B layout
    #pragma unroll
    for (int k = 0; k < 4; ++k) { aW[k] = 0ULL; aR[k] = 0ULL; aG[k] = 0ULL; aB[k] = 0ULL; }

    // ---- odd offsets first, phase-B layout: cols (cx+1, cx+2) ----
    #pragma unroll 1
    for (int ox = -5; ox <= 5; ox += 2)
        process_ox<true>(ysB + cx + ox - 1, yreg, r0t, aW, aR, aG, aB);

    // ---- re-align phase B -> phase A: lane L's lo(cx) = lane L-1's hi ----
    #pragma unroll
    for (int k = 0; k < 4; ++k) {
        float lo, hi;
        up2(aW[k], lo, hi); aW[k] = pk(__shfl_up_sync(FULLM, hi, 1), lo);
        up2(aR[k], lo, hi); aR[k] = pk(__shfl_up_sync(FULLM, hi, 1), lo);
        up2(aG[k], lo, hi); aG[k] = pk(__shfl_up_sync(FULLM, hi, 1), lo);
        up2(aB[k], lo, hi); aB[k] = pk(__shfl_up_sync(FULLM, hi, 1), lo);
    }

    // ---- even offsets, phase-A layout: cols (cx, cx+1) ----
    #pragma unroll 1
    for (int ox = -4; ox <= 4; ox += 2)
        process_ox<false>(ys + cx + ox, yreg, r0t, aW, aR, aG, aB);

    // ---- write output (lanes 1..30 own 60 output cols) ----
    if (lane >= 1 && lane <= 30) {
        int gc = (colBase + 2 * (lane - 1)) & MASK;   // even; pair contiguous
        float* ob = out + (size_t)n * 3 * PLANE;
        #pragma unroll
        for (int k = 0; k < 4; ++k) {
            float wlo, whi, rlo, rhi, glo, ghi, blo, bhi;
            up2(aW[k], wlo, whi);
            up2(aR[k], rlo, rhi);
            up2(aG[k], glo, ghi);
            up2(aB[k], blo, bhi);
            float il = 1.0f / wlo, ih = 1.0f / whi;
            int gr = rowBase + r0t + k;
            float* o0 = ob + gr * W_IMG + gc;
            *(float2*)(o0)             = make_float2(fminf(fmaxf(rlo * il, 0.f), 1.f),
                                                     fminf(fmaxf(rhi * ih, 0.f), 1.f));
            *(float2*)(o0 + PLANE)     = make_float2(fminf(fmaxf(glo * il, 0.f), 1.f),
                                                     fminf(fmaxf(ghi * ih, 0.f), 1.f));
            *(float2*)(o0 + 2 * PLANE) = make_float2(fminf(fmaxf(blo * il, 0.f), 1.f),
                                                     fminf(fmaxf(bhi * ih, 0.f), 1.f));
        }
    }
}

extern "C" void kernel_launch(void* const* d_in, const int* in_sizes, int n_in,
                              void* d_out, int out_size)
{
    (void)in_sizes; (void)n_in; (void)out_size;
    const float* x = (const float*)d_in[0];
    float* out = (float*)d_out;

    dim3 block(32, WARPS, 1);
    dim3 grid((W_IMG + OUT_COLS - 1) / OUT_COLS,   // 9 (last tile wraps; duplicate
              W_IMG / TILE_ROWS,                   //    writes are bitwise identical)
              2);                                  // 9*32*2 = 576 = one wave @4/SM
    nlm_kernel<<<grid, block>>>(x, out);
}